// round 1
// baseline (speedup 1.0000x reference)
#include <cuda_runtime.h>
#include <cstddef>

#define BB 2048
#define NN 512
#define XX 32
#define HH 64
#define TILE_B 16
#define THREADS 256
#define NBLK (BB / TILE_B)   /* 128 */
#define HPITCH 20            /* padded row pitch (floats), 80B = 16B aligned */

__device__ __forceinline__ unsigned long long pack2(float v) {
    unsigned long long r;
    asm("mov.b64 %0, {%1, %1};" : "=l"(r) : "f"(v));
    return r;
}
__device__ __forceinline__ unsigned long long fma2(unsigned long long a,
                                                   unsigned long long b,
                                                   unsigned long long c) {
    unsigned long long d;
    asm("fma.rn.f32x2 %0, %1, %2, %3;" : "=l"(d) : "l"(a), "l"(b), "l"(c));
    return d;
}
__device__ __forceinline__ void unpack2(unsigned long long v, float& lo, float& hi) {
    asm("mov.b64 {%0, %1}, %2;" : "=f"(lo), "=f"(hi) : "l"(v));
}

__device__ __forceinline__ float sigmoidf_fast(float x) {
    // 1/(1+exp(-x)); safe at extremes: exp->inf gives 0, exp->0 gives 1
    return __fdividef(1.0f, 1.0f + __expf(-x));
}
__device__ __forceinline__ float tanhf_fast(float x) {
    // 2/(1+exp(-2x)) - 1; safe at extremes (exp->inf => -1, exp->0 => +1)
    return __fdividef(2.0f, 1.0f + __expf(-2.0f * x)) - 1.0f;
}

__global__ void __launch_bounds__(THREADS, 1)
timelstm_kernel(const float* __restrict__ x,
                const float* __restrict__ ig_w_c, const float* __restrict__ ig_w_h,
                const float* __restrict__ ig_w_x, const float* __restrict__ ig_b,
                const float* __restrict__ fg_w_c, const float* __restrict__ fg_w_h,
                const float* __restrict__ fg_w_x, const float* __restrict__ fg_b,
                const float* __restrict__ in_w_h, const float* __restrict__ in_w_x,
                const float* __restrict__ in_b,
                const float* __restrict__ og_w_cn, const float* __restrict__ og_w_h,
                const float* __restrict__ og_w_x, const float* __restrict__ og_b,
                float* __restrict__ out)
{
    // h_sh/x_sh are [k][row] with padded pitch so rows 0..15 of one k are a
    // contiguous, 16B-aligned 64B run (vector LDS, broadcast across the warp).
    __shared__ __align__(16) float h_sh[HH * HPITCH];
    __shared__ __align__(16) float x_sh[XX * HPITCH];
    __shared__ float g_sh[4][TILE_B][HH];   // gate pre-activations
    __shared__ float cm_sh[TILE_B][HH];
    __shared__ float wc_sh[3][HH];          // ig_w_c, fg_w_c, og_w_cn

    const int tid  = threadIdx.x;
    const int b0   = blockIdx.x * TILE_B;
    const int gate = tid >> 6;      // 0..3 : ig, fg, in, og
    const int hid  = tid & 63;      // output channel

    // ---- per-thread weight rows into registers ----
    const float* Wh; const float* Wx; const float* Bv;
    if (gate == 0)      { Wh = ig_w_h; Wx = ig_w_x; Bv = ig_b; }
    else if (gate == 1) { Wh = fg_w_h; Wx = fg_w_x; Bv = fg_b; }
    else if (gate == 2) { Wh = in_w_h; Wx = in_w_x; Bv = in_b; }
    else                { Wh = og_w_h; Wx = og_w_x; Bv = og_b; }

    float wh[HH], wx[XX];
    #pragma unroll
    for (int k = 0; k < HH; k++) wh[k] = Wh[hid * HH + k];
    #pragma unroll
    for (int k = 0; k < XX; k++) wx[k] = Wx[hid * XX + k];
    const float bias = Bv[hid];

    if (tid < HH) {
        wc_sh[0][tid] = ig_w_c[tid];
        wc_sh[1][tid] = fg_w_c[tid];
        wc_sh[2][tid] = og_w_cn[tid];
    }
    // init state to zero
    for (int i = tid; i < HH * HPITCH; i += THREADS) h_sh[i] = 0.0f;
    for (int i = tid; i < TILE_B * HH; i += THREADS) (&cm_sh[0][0])[i] = 0.0f;

    // ---- x prefetch registers: thread covers (row=tid/16, k=tid%16 and +16) ----
    const int xr = tid >> 4;   // 0..15
    const int xk = tid & 15;   // 0..15
    const float* xptr = x + ((size_t)(b0 + xr) * NN) * XX + xk;
    float xv0 = xptr[0];
    float xv1 = xptr[16];

    for (int t = 0; t < NN; t++) {
        // deposit prefetched x_t (safe: prior phase-A x reads completed before
        // the previous mid-step barrier)
        x_sh[xk * HPITCH + xr]        = xv0;
        x_sh[(xk + 16) * HPITCH + xr] = xv1;
        __syncthreads();   // x_sh ready AND previous phase-B h_sh/cm writes visible

        // prefetch x_{t+1} (latency hidden under phase A)
        if (t + 1 < NN) {
            const float* p = xptr + (size_t)(t + 1) * XX;
            xv0 = p[0];
            xv1 = p[16];
        }

        // ---- phase A: gate pre-activations, 16 rows per thread, packed f32x2 ----
        unsigned long long acc[8];
        {
            unsigned long long b2 = pack2(bias);
            #pragma unroll
            for (int i = 0; i < 8; i++) acc[i] = b2;
        }
        #pragma unroll
        for (int k = 0; k < XX; k++) {
            unsigned long long w2 = pack2(wx[k]);
            const ulonglong2* p = reinterpret_cast<const ulonglong2*>(&x_sh[k * HPITCH]);
            #pragma unroll
            for (int j = 0; j < 4; j++) {
                ulonglong2 v = p[j];
                acc[2 * j]     = fma2(v.x, w2, acc[2 * j]);
                acc[2 * j + 1] = fma2(v.y, w2, acc[2 * j + 1]);
            }
        }
        #pragma unroll
        for (int k = 0; k < HH; k++) {
            unsigned long long w2 = pack2(wh[k]);
            const ulonglong2* p = reinterpret_cast<const ulonglong2*>(&h_sh[k * HPITCH]);
            #pragma unroll
            for (int j = 0; j < 4; j++) {
                ulonglong2 v = p[j];
                acc[2 * j]     = fma2(v.x, w2, acc[2 * j]);
                acc[2 * j + 1] = fma2(v.y, w2, acc[2 * j + 1]);
            }
        }
        #pragma unroll
        for (int i = 0; i < 8; i++) {
            float lo, hi;
            unpack2(acc[i], lo, hi);
            g_sh[gate][2 * i][hid]     = lo;
            g_sh[gate][2 * i + 1][hid] = hi;
        }
        __syncthreads();   // g_sh ready; phase A done reading h_sh/x_sh

        // ---- phase B: activations + state update. thread = (hh, 4 contiguous rows) ----
        {
            const int rb = tid >> 6;     // 0..3 -> rows rb*4 .. rb*4+3
            const int hh = tid & 63;
            const float wic = wc_sh[0][hh];
            const float wfc = wc_sh[1][hh];
            const float woc = wc_sh[2][hh];
            float hv[4];
            #pragma unroll
            for (int rr = 0; rr < 4; rr++) {
                const int r = rb * 4 + rr;
                const float cm  = cm_sh[r][hh];
                const float ig  = sigmoidf_fast(wic * cm + g_sh[0][r][hh]);
                const float fg  = sigmoidf_fast(wfc * cm + g_sh[1][r][hh]);
                const float inn = tanhf_fast(g_sh[2][r][hh]);
                const float cmn = fg * cm + ig * inn;
                const float og  = sigmoidf_fast(woc * cmn + g_sh[3][r][hh]);
                hv[rr] = og * tanhf_fast(cmn);
                cm_sh[r][hh] = cmn;
            }
            // h_sh[hh][rb*4 .. +3] : 16B-aligned vector store
            *reinterpret_cast<float4*>(&h_sh[hh * HPITCH + rb * 4]) =
                make_float4(hv[0], hv[1], hv[2], hv[3]);
            if (t == NN - 1) {
                #pragma unroll
                for (int rr = 0; rr < 4; rr++)
                    out[(size_t)(b0 + rb * 4 + rr) * HH + hh] = hv[rr];
            }
        }
        // no barrier here: next-iteration x_sh deposit touches a different array,
        // and the loop-top barrier orders h_sh/cm before the next phase A.
    }
}

extern "C" void kernel_launch(void* const* d_in, const int* in_sizes, int n_in,
                              void* d_out, int out_size) {
    const float* x       = (const float*)d_in[0];
    const float* ig_w_c  = (const float*)d_in[1];
    const float* ig_w_h  = (const float*)d_in[2];
    const float* ig_w_x  = (const float*)d_in[3];
    const float* ig_b    = (const float*)d_in[4];
    const float* fg_w_c  = (const float*)d_in[5];
    const float* fg_w_h  = (const float*)d_in[6];
    const float* fg_w_x  = (const float*)d_in[7];
    const float* fg_b    = (const float*)d_in[8];
    const float* in_w_h  = (const float*)d_in[9];
    const float* in_w_x  = (const float*)d_in[10];
    const float* in_b    = (const float*)d_in[11];
    const float* og_w_cn = (const float*)d_in[12];
    const float* og_w_h  = (const float*)d_in[13];
    const float* og_w_x  = (const float*)d_in[14];
    const float* og_b    = (const float*)d_in[15];
    float* out = (float*)d_out;

    timelstm_kernel<<<NBLK, THREADS>>>(
        x, ig_w_c, ig_w_h, ig_w_x, ig_b,
        fg_w_c, fg_w_h, fg_w_x, fg_b,
        in_w_h, in_w_x, in_b,
        og_w_cn, og_w_h, og_w_x, og_b, out);
}